// round 15
// baseline (speedup 1.0000x reference)
#include <cuda_runtime.h>
#include <cuda_fp16.h>
#include <cuda_bf16.h>
#include <cstdint>

// Problem constants
#define BSZ 512
#define SEG 256
#define HID 1024
#define SLOTS 16

// ---------------- scratch (device globals; no allocation allowed) ----------
__device__ float  g_query[SLOTS * HID];     // latent_queries @ Wq^T + bq
__device__ float  g_qt[SLOTS * HID];        // query @ Wk
__device__ float  g_c[SLOTS];               // query . bk
__device__ float  g_cb[HID];                // Wo @ bv + bo
__device__ __half g_WcH[HID * HID];         // Wo @ Wv  (fp16)
__device__ __half g_WvTH[HID * HID];        // Wv^T     (fp16)
__device__ __half g_WoH[HID * HID];         // Wo       (fp16)
__device__ __half g_mH[BSZ * SLOTS * HID];  // attn slots (fp16)

// ---------------- helpers ----------------------------------------------------
__device__ __forceinline__ unsigned su32(const void* p) {
    return (unsigned)__cvta_generic_to_shared(p);
}
__device__ __forceinline__ uint32_t h2bits(__half2 h) {
    return *reinterpret_cast<uint32_t*>(&h);
}
__device__ __forceinline__ void mma_f16(float* d, const uint32_t* a,
                                        uint32_t b0, uint32_t b1) {
    asm volatile(
        "mma.sync.aligned.m16n8k16.row.col.f32.f16.f16.f32 "
        "{%0,%1,%2,%3}, {%4,%5,%6,%7}, {%8,%9}, {%0,%1,%2,%3};"
        : "+f"(d[0]), "+f"(d[1]), "+f"(d[2]), "+f"(d[3])
        : "r"(a[0]), "r"(a[1]), "r"(a[2]), "r"(a[3]), "r"(b0), "r"(b1));
}
__device__ __forceinline__ void ldsm_x4(uint32_t& t0, uint32_t& t1,
                                        uint32_t& t2, uint32_t& t3,
                                        unsigned addr) {
    asm volatile(
        "ldmatrix.sync.aligned.m8n8.x4.shared.b16 {%0,%1,%2,%3}, [%4];"
        : "=r"(t0), "=r"(t1), "=r"(t2), "=r"(t3) : "r"(addr));
}
__device__ __forceinline__ void ldsm_x4_trans(uint32_t& t0, uint32_t& t1,
                                              uint32_t& t2, uint32_t& t3,
                                              unsigned addr) {
    asm volatile(
        "ldmatrix.sync.aligned.m8n8.x4.trans.shared.b16 {%0,%1,%2,%3}, [%4];"
        : "=r"(t0), "=r"(t1), "=r"(t2), "=r"(t3) : "r"(addr));
}

// ---------------- tiny prelim kernels --------------------------------------
__global__ void k_query(const float* __restrict__ Lq, const float* __restrict__ Wq,
                        const float* __restrict__ bq, float* __restrict__ Q) {
    const int lane = threadIdx.x & 31;
    const int wg = (blockIdx.x * blockDim.x + threadIdx.x) >> 5;  // 0..511
    for (int o = wg; o < SLOTS * HID; o += 512) {
        const int s = o >> 10, e = o & 1023;
        const float4* a = (const float4*)(Lq + (size_t)s * HID);
        const float4* w = (const float4*)(Wq + (size_t)e * HID);
        float p = 0.f;
        #pragma unroll
        for (int i = 0; i < 8; i++) {
            float4 xa = a[i * 32 + lane];
            float4 xw = w[i * 32 + lane];
            p += xa.x * xw.x + xa.y * xw.y + xa.z * xw.z + xa.w * xw.w;
        }
        #pragma unroll
        for (int off = 16; off; off >>= 1) p += __shfl_xor_sync(0xffffffffu, p, off);
        if (lane == 0) Q[o] = p + bq[e];
    }
}

__global__ void k_qtilde(const float* __restrict__ Q, const float* __restrict__ Wk,
                         const float* __restrict__ bk, float* __restrict__ QT,
                         float* __restrict__ CV) {
    const int s = blockIdx.x >> 2;
    const int chunk = blockIdx.x & 3;
    const int n = chunk * 256 + threadIdx.x;
    __shared__ float qs[HID];
    #pragma unroll
    for (int u = 0; u < 4; u++) qs[u * 256 + threadIdx.x] = Q[s * HID + u * 256 + threadIdx.x];
    __syncthreads();
    float acc = 0.f;
    #pragma unroll 8
    for (int d = 0; d < HID; d++) acc += qs[d] * Wk[(size_t)d * HID + n];
    QT[s * HID + n] = acc;
    if (chunk == 0 && threadIdx.x < 32) {
        float p = 0.f;
        for (int d = threadIdx.x; d < HID; d += 32) p += qs[d] * bk[d];
        #pragma unroll
        for (int off = 16; off; off >>= 1) p += __shfl_xor_sync(0xffffffffu, p, off);
        if (threadIdx.x == 0) CV[s] = p;
    }
}

__global__ void k_cb(const float* __restrict__ Wo, const float* __restrict__ bv,
                     const float* __restrict__ bo, float* __restrict__ CB) {
    const int e = (blockIdx.x * blockDim.x + threadIdx.x) >> 5;
    const int lane = threadIdx.x & 31;
    const float* row = Wo + (size_t)e * HID;
    float p = 0.f;
    for (int d = lane; d < HID; d += 32) p += row[d] * bv[d];
    #pragma unroll
    for (int off = 16; off; off >>= 1) p += __shfl_xor_sync(0xffffffffu, p, off);
    if (lane == 0) CB[e] = p + bo[e];
}

// WvTH[n,d] = fp16(Wv[d,n])
__global__ void k_transposeH(const float* __restrict__ A, __half* __restrict__ AT) {
    __shared__ float t[32][33];
    const int bx = blockIdx.x * 32, by = blockIdx.y * 32;
    const int x = threadIdx.x, y0 = threadIdx.y;
    #pragma unroll
    for (int i = 0; i < 32; i += 8)
        t[y0 + i][x] = A[(size_t)(by + y0 + i) * HID + bx + x];
    __syncthreads();
    #pragma unroll
    for (int i = 0; i < 32; i += 8)
        AT[(size_t)(bx + y0 + i) * HID + by + x] = __float2half_rn(t[x][y0 + i]);
}

// out[i] = fp16(in[i])
__global__ void k_tohalf(const float* __restrict__ in, __half* __restrict__ out) {
    const int i = blockIdx.x * blockDim.x + threadIdx.x;
    float4 f = ((const float4*)in)[i];
    uint2 o;
    o.x = h2bits(__floats2half2_rn(f.x, f.y));
    o.y = h2bits(__floats2half2_rn(f.z, f.w));
    ((uint2*)out)[i] = o;
}

// ---------------- fp16 mma.sync GEMM: D[M,N] = A[M,K] @ B[N,K]^T (+bias) ----
// m16n8k16, fp32 accum. BK=64 halves, double-buffered smem, ldmatrix frags.
template <bool HALF_OUT>
__global__ void __launch_bounds__(256, 2)
hgemm_kernel(const __half* __restrict__ A, const __half* __restrict__ B,
             void* __restrict__ Cv, const float* __restrict__ bias,
             int M, int N, int K) {
    __shared__ __align__(16) uint32_t As[2][4096];   // 128 rows x 32 words
    __shared__ __align__(16) uint32_t Bs[2][4096];

    const int tid = threadIdx.x;
    const int warp = tid >> 5, lane = tid & 31;
    const int m0 = blockIdx.y * 128;
    const int n0 = blockIdx.x * 128;
    const int wm = (warp & 3) * 32;
    const int wn = (warp >> 2) * 64;
    const int qr = lane >> 2;
    const int qc = lane & 3;
    // ldmatrix lane mapping: lr = row within 16-row group, wgl = k-halfgroup
    const int lr = (lane & 7) + ((lane >> 3) & 1) * 8;
    const int wgl = (lane >> 4) & 1;

    float acc[2][8][4];
    #pragma unroll
    for (int i = 0; i < 2; i++)
        #pragma unroll
        for (int j = 0; j < 8; j++)
            #pragma unroll
            for (int v = 0; v < 4; v++) acc[i][j][v] = 0.f;

    // staging: v = u*256+tid; r = v>>3 (row), g = v&7 (uint4 group of 8 halves)
    uint4 pa[4], pb[4];
    #pragma unroll
    for (int u = 0; u < 4; u++) {
        int v = u * 256 + tid;
        int r = v >> 3, g = v & 7;
        pa[u] = *(const uint4*)(A + (size_t)(m0 + r) * K + g * 8);
        pb[u] = *(const uint4*)(B + (size_t)(n0 + r) * K + g * 8);
    }
    #pragma unroll
    for (int u = 0; u < 4; u++) {
        int v = u * 256 + tid;
        int r = v >> 3, g = v & 7;
        int phys = r * 32 + (((g ^ r) & 7) << 2);
        *(uint4*)&As[0][phys] = pa[u];
        *(uint4*)&Bs[0][phys] = pb[u];
    }
    __syncthreads();

    const int ar0 = wm + lr;
    const int ar1 = wm + 16 + lr;
    const int br0 = wn + lr, br1 = wn + 16 + lr, br2 = wn + 32 + lr, br3 = wn + 48 + lr;

    const int nchunk = K / 64;
    #pragma unroll 1
    for (int ck = 0; ck < nchunk; ck++) {
        const int cur = ck & 1;
        if (ck + 1 < nchunk) {
            const int k0 = (ck + 1) * 64;
            #pragma unroll
            for (int u = 0; u < 4; u++) {
                int v = u * 256 + tid;
                int r = v >> 3, g = v & 7;
                pa[u] = *(const uint4*)(A + (size_t)(m0 + r) * K + k0 + g * 8);
                pb[u] = *(const uint4*)(B + (size_t)(n0 + r) * K + k0 + g * 8);
            }
        }
        const unsigned aBase = su32(As[cur]);
        const unsigned bBase = su32(Bs[cur]);
        #pragma unroll
        for (int kk = 0; kk < 4; kk++) {           // 4 x k16 = 64 halves
            const int g = 2 * kk + wgl;
            uint32_t af0[4], af1[4], tb[4];
            ldsm_x4(af0[0], af0[1], af0[2], af0[3],
                    aBase + (unsigned)(ar0 * 128 + (((g ^ ar0) & 7) << 4)));
            ldsm_x4(af1[0], af1[1], af1[2], af1[3],
                    aBase + (unsigned)(ar1 * 128 + (((g ^ ar1) & 7) << 4)));
            const int brs[4] = {br0, br1, br2, br3};
            #pragma unroll
            for (int njb = 0; njb < 4; njb++) {
                const int br = brs[njb];
                ldsm_x4(tb[0], tb[1], tb[2], tb[3],
                        bBase + (unsigned)(br * 128 + (((g ^ br) & 7) << 4)));
                mma_f16(acc[0][2 * njb],     af0, tb[0], tb[2]);
                mma_f16(acc[0][2 * njb + 1], af0, tb[1], tb[3]);
                mma_f16(acc[1][2 * njb],     af1, tb[0], tb[2]);
                mma_f16(acc[1][2 * njb + 1], af1, tb[1], tb[3]);
            }
        }
        if (ck + 1 < nchunk) {
            uint32_t* An = As[cur ^ 1];
            uint32_t* Bn = Bs[cur ^ 1];
            #pragma unroll
            for (int u = 0; u < 4; u++) {
                int v = u * 256 + tid;
                int r = v >> 3, g = v & 7;
                int phys = r * 32 + (((g ^ r) & 7) << 2);
                *(uint4*)&An[phys] = pa[u];
                *(uint4*)&Bn[phys] = pb[u];
            }
        }
        __syncthreads();
    }

    #pragma unroll
    for (int mi = 0; mi < 2; mi++) {
        const int r = m0 + wm + mi * 16 + qr;
        #pragma unroll
        for (int nj = 0; nj < 8; nj++) {
            const int cc = n0 + wn + nj * 8 + 2 * qc;
            float b0 = 0.f, b1 = 0.f;
            if (bias) { b0 = bias[cc]; b1 = bias[cc + 1]; }
            float v00 = acc[mi][nj][0] + b0, v01 = acc[mi][nj][1] + b1;
            float v10 = acc[mi][nj][2] + b0, v11 = acc[mi][nj][3] + b1;
            if (HALF_OUT) {
                __half* C = (__half*)Cv;
                *(__half2*)(C + (size_t)r * N + cc) = __floats2half2_rn(v00, v01);
                *(__half2*)(C + (size_t)(r + 8) * N + cc) = __floats2half2_rn(v10, v11);
            } else {
                float* C = (float*)Cv;
                *(float2*)(C + (size_t)r * N + cc) = make_float2(v00, v01);
                *(float2*)(C + (size_t)(r + 8) * N + cc) = make_float2(v10, v11);
            }
        }
    }
}

// ---------------- attention v5: fp16 TC, ldmatrix frags, occ=2 --------------
// Per CTA = one batch; per 32-token tile:
//   S[16,32] = QT @ Xtile^T  (f16 MMA, K split over 8 warps, fp16 partials)
//   w = exp((S + cv)*scale + lg)
//   m[16,1024] += w @ Xtile  (f16 MMA, ldmatrix.trans B frags)
#define QSTB 2064                  // QT row stride bytes
#define XSTB 2064                  // X  row stride bytes
#define WSB  80                    // ws row stride bytes
#define RSTH 40                    // red row stride halves
// byte offsets
#define A4_QT  0
#define A4_XS  33024               // + 16*2064
#define A4_RED 99072               // + 32*2064
#define A4_WS  109312              // + 8*16*40*2
#define A4_LS  110592              // + 16*80
#define A4_CV  110656
#define A4_LG  110720
#define A4_TOTAL 111744            // + 256*4

__global__ void __launch_bounds__(256, 2)
attn5_kernel(const float* __restrict__ X, const float* __restrict__ LG,
             const float* __restrict__ QT, const float* __restrict__ CV,
             __half* __restrict__ Mout) {
    extern __shared__ __align__(16) char smc[];
    float* Ls  = (float*)(smc + A4_LS);
    float* cvs = (float*)(smc + A4_CV);
    float* lgs = (float*)(smc + A4_LG);

    const int b = blockIdx.x;
    const int tid = threadIdx.x;
    const int warp = tid >> 5, lane = tid & 31;
    const int qr = lane >> 2, qc = lane & 3;
    const int wn = warp * 128;     // m-GEMM dim band
    const int lr = (lane & 7) + ((lane >> 3) & 1) * 8;
    const int wgl = (lane >> 4) & 1;

    // stage QT as fp16: v = float4 index; row = v>>8, g = v&255
    const float4* QT4 = (const float4*)QT;
    #pragma unroll 8
    for (int u = 0; u < 16; u++) {
        int v = u * 256 + tid;
        int s = v >> 8, g = v & 255;
        float4 f = QT4[v];
        uint2 o;
        o.x = h2bits(__floats2half2_rn(f.x, f.y));
        o.y = h2bits(__floats2half2_rn(f.z, f.w));
        *(uint2*)(smc + A4_QT + s * QSTB + g * 8) = o;
    }
    if (tid < 16) { cvs[tid] = CV[tid]; Ls[tid] = 0.f; }
    lgs[tid] = LG[b * SEG + tid];

    float macc[16][4];
    #pragma unroll
    for (int i = 0; i < 16; i++)
        #pragma unroll
        for (int v = 0; v < 4; v++) macc[i][v] = 0.f;

    // ldmatrix (trans) lane parts for m-GEMM B frags
    const int row_sel = lane & 7, mat = lane >> 3;
    const int tok_part = ((mat & 1) << 3) + row_sel;
    const int dim_part = (mat >> 1) << 3;

    // score-GEMM ldmatrix bases (lane-fixed row parts)
    const unsigned qtB = su32(smc) + A4_QT + (unsigned)(lr * QSTB);
    const unsigned xs0 = su32(smc) + A4_XS + (unsigned)(lr * XSTB);
    const unsigned xs1 = xs0 + 16u * XSTB;

    const float4* Xb4 = (const float4*)(X + (size_t)b * SEG * HID);

    #pragma unroll 1
    for (int tile = 0; tile < SEG / 32; tile++) {
        __syncthreads();
        // stage 32 tokens fp16: [token][dim]
        #pragma unroll 8
        for (int u = 0; u < 32; u++) {
            int v = u * 256 + tid;
            int r = v >> 8, g = v & 255;
            float4 f = Xb4[(tile * 32 + r) * 256 + g];
            uint2 o;
            o.x = h2bits(__floats2half2_rn(f.x, f.y));
            o.y = h2bits(__floats2half2_rn(f.z, f.w));
            *(uint2*)(smc + A4_XS + r * XSTB + g * 8) = o;
        }
        __syncthreads();

        // ---- score GEMM: warp K-slice [warp*128, +128) ----
        float sacc[4][4];
        #pragma unroll
        for (int j = 0; j < 4; j++)
            #pragma unroll
            for (int v = 0; v < 4; v++) sacc[j][v] = 0.f;
        #pragma unroll
        for (int kk = 0; kk < 8; kk++) {
            const unsigned kb2 = (unsigned)((warp * 128 + kk * 16 + wgl * 8) * 2);
            uint32_t a[4], t[4];
            ldsm_x4(a[0], a[1], a[2], a[3], qtB + kb2);
            ldsm_x4(t[0], t[1], t[2], t[3], xs0 + kb2);
            mma_f16(sacc[0], a, t[0], t[2]);
            mma_f16(sacc[1], a, t[1], t[3]);
            ldsm_x4(t[0], t[1], t[2], t[3], xs1 + kb2);
            mma_f16(sacc[2], a, t[0], t[2]);
            mma_f16(sacc[3], a, t[1], t[3]);
        }
        // write partials (fp16; partial magnitudes ~0.2 -> error negligible)
        #pragma unroll
        for (int nj = 0; nj < 4; nj++) {
            const int col = nj * 8 + 2 * qc;
            *(__half2*)(smc + A4_RED + (warp * 640 + qr * RSTH + col) * 2) =
                __floats2half2_rn(sacc[nj][0], sacc[nj][1]);
            *(__half2*)(smc + A4_RED + (warp * 640 + (qr + 8) * RSTH + col) * 2) =
                __floats2half2_rn(sacc[nj][2], sacc[nj][3]);
        }
        __syncthreads();

        // ---- reduce + softmax weights (warp = one slot row per h) ----
        #pragma unroll
        for (int h = 0; h < 2; h++) {
            const int row = h * 8 + warp, tok = lane;
            float s = 0.f;
            #pragma unroll
            for (int w = 0; w < 8; w++)
                s += __half2float(*(const __half*)(
                    smc + A4_RED + (w * 640 + row * RSTH + tok) * 2));
            float sc = (s + cvs[row]) * 0.03125f + lgs[tile * 32 + tok];
            float wv = __expf(sc);
            *(__half*)(smc + A4_WS + row * WSB + tok * 2) = __float2half_rn(wv);
            #pragma unroll
            for (int off = 16; off; off >>= 1)
                wv += __shfl_xor_sync(0xffffffffu, wv, off);
            if (lane == 0) Ls[row] += wv;
        }
        __syncthreads();

        // ---- m GEMM: m[16, wn..wn+128) += w[16,32] @ Xtile ----
        #pragma unroll
        for (int kk = 0; kk < 2; kk++) {
            const int kt = kk * 16;
            uint32_t a[4];
            a[0] = *(const uint32_t*)(smc + A4_WS + qr * WSB + (kt + 2 * qc) * 2);
            a[1] = *(const uint32_t*)(smc + A4_WS + (qr + 8) * WSB + (kt + 2 * qc) * 2);
            a[2] = *(const uint32_t*)(smc + A4_WS + qr * WSB + (kt + 2 * qc) * 2 + 16);
            a[3] = *(const uint32_t*)(smc + A4_WS + (qr + 8) * WSB + (kt + 2 * qc) * 2 + 16);
            #pragma unroll
            for (int njb = 0; njb < 8; njb++) {
                unsigned addr = su32(smc + A4_XS + (kt + tok_part) * XSTB +
                                     (wn + njb * 16 + dim_part) * 2);
                uint32_t t0, t1, t2, t3;
                ldsm_x4_trans(t0, t1, t2, t3, addr);
                mma_f16(macc[2 * njb],     a, t0, t1);
                mma_f16(macc[2 * njb + 1], a, t2, t3);
            }
        }
    }
    __syncthreads();  // Ls final

    const float inv0 = 1.0f / Ls[qr];
    const float inv1 = 1.0f / Ls[qr + 8];
    __half* m0p = Mout + ((size_t)b * SLOTS + qr) * HID;
    __half* m1p = Mout + ((size_t)b * SLOTS + qr + 8) * HID;
    #pragma unroll
    for (int nj = 0; nj < 16; nj++) {
        const int cc = wn + nj * 8 + 2 * qc;
        *(__half2*)(m0p + cc) =
            __floats2half2_rn(macc[nj][0] * inv0, macc[nj][1] * inv0);
        *(__half2*)(m1p + cc) =
            __floats2half2_rn(macc[nj][2] * inv1, macc[nj][3] * inv1);
    }
}

// ---------------- launcher ---------------------------------------------------
extern "C" void kernel_launch(void* const* d_in, const int* in_sizes, int n_in,
                              void* d_out, int out_size) {
    (void)in_sizes; (void)n_in; (void)out_size;
    const float* X  = (const float*)d_in[0];   // segment_states [512,256,1024]
    const float* LG = (const float*)d_in[1];   // importance_logits [512,256]
    const float* Lq = (const float*)d_in[2];   // latent_queries [16,1024]
    const float* Wq = (const float*)d_in[3];
    const float* bq = (const float*)d_in[4];
    const float* Wk = (const float*)d_in[5];
    const float* bk = (const float*)d_in[6];
    const float* Wv = (const float*)d_in[7];
    const float* bv = (const float*)d_in[8];
    const float* Wo = (const float*)d_in[9];
    const float* bo = (const float*)d_in[10];
    float* out = (float*)d_out;

    void *pQ, *pQT, *pC, *pCB, *pWcH, *pWvTH, *pWoH, *pMH;
    cudaGetSymbolAddress(&pQ, g_query);
    cudaGetSymbolAddress(&pQT, g_qt);
    cudaGetSymbolAddress(&pC, g_c);
    cudaGetSymbolAddress(&pCB, g_cb);
    cudaGetSymbolAddress(&pWcH, g_WcH);
    cudaGetSymbolAddress(&pWvTH, g_WvTH);
    cudaGetSymbolAddress(&pWoH, g_WoH);
    cudaGetSymbolAddress(&pMH, g_mH);
    float*  Q    = (float*)pQ;
    float*  QT   = (float*)pQT;
    float*  C    = (float*)pC;
    float*  CB   = (float*)pCB;
    __half* WcH  = (__half*)pWcH;
    __half* WvTH = (__half*)pWvTH;
    __half* WoH  = (__half*)pWoH;
    __half* MH   = (__half*)pMH;

    cudaFuncSetAttribute(attn5_kernel, cudaFuncAttributeMaxDynamicSharedMemorySize,
                         A4_TOTAL);

    // launch order puts attn5 in the ncu-profiled slot (#4)
    k_query<<<64, 256>>>(Lq, Wq, bq, Q);
    k_qtilde<<<64, 256>>>(Q, Wk, bk, QT, C);
    k_cb<<<128, 256>>>(Wo, bv, bo, CB);
    // attention -> m  (fp16 tensor cores, single X pass)
    attn5_kernel<<<BSZ, 256, A4_TOTAL>>>(X, LG, QT, C, MH);
    k_transposeH<<<dim3(32, 32), dim3(32, 8)>>>(Wv, WvTH);
    k_tohalf<<<(HID * HID / 4) / 256, 256>>>(Wo, WoH);
    // Wc = Wo @ Wv  (fp16 GEMM, fp16 output)
    hgemm_kernel<true><<<dim3(HID / 128, HID / 128), 256>>>(
        WoH, WvTH, WcH, nullptr, HID, HID, HID);
    // out = m @ Wc^T + cb  (fp16 GEMM, fp32 output)
    hgemm_kernel<false><<<dim3(HID / 128, (BSZ * SLOTS) / 128), 256>>>(
        MH, WcH, out, CB, BSZ * SLOTS, HID, HID);
}

// round 16
// speedup vs baseline: 1.0241x; 1.0241x over previous
#include <cuda_runtime.h>
#include <cuda_fp16.h>
#include <cuda_bf16.h>
#include <cstdint>

// Problem constants
#define BSZ 512
#define SEG 256
#define HID 1024
#define SLOTS 16

// ---------------- scratch (device globals; no allocation allowed) ----------
__device__ float  g_query[SLOTS * HID];     // latent_queries @ Wq^T + bq
__device__ float  g_qt[SLOTS * HID];        // query @ Wk
__device__ float  g_c[SLOTS];               // query . bk
__device__ float  g_cb[HID];                // Wo @ bv + bo
__device__ __half g_WcH[HID * HID];         // Wo @ Wv  (fp16)
__device__ __half g_WvTH[HID * HID];        // Wv^T     (fp16)
__device__ __half g_WoH[HID * HID];         // Wo       (fp16)
__device__ __half g_mH[BSZ * SLOTS * HID];  // attn slots (fp16)

// ---------------- helpers ----------------------------------------------------
__device__ __forceinline__ unsigned su32(const void* p) {
    return (unsigned)__cvta_generic_to_shared(p);
}
__device__ __forceinline__ uint32_t h2bits(__half2 h) {
    return *reinterpret_cast<uint32_t*>(&h);
}
__device__ __forceinline__ void mma_f16(float* d, const uint32_t* a,
                                        uint32_t b0, uint32_t b1) {
    asm volatile(
        "mma.sync.aligned.m16n8k16.row.col.f32.f16.f16.f32 "
        "{%0,%1,%2,%3}, {%4,%5,%6,%7}, {%8,%9}, {%0,%1,%2,%3};"
        : "+f"(d[0]), "+f"(d[1]), "+f"(d[2]), "+f"(d[3])
        : "r"(a[0]), "r"(a[1]), "r"(a[2]), "r"(a[3]), "r"(b0), "r"(b1));
}
__device__ __forceinline__ void ldsm_x4(uint32_t& t0, uint32_t& t1,
                                        uint32_t& t2, uint32_t& t3,
                                        unsigned addr) {
    asm volatile(
        "ldmatrix.sync.aligned.m8n8.x4.shared.b16 {%0,%1,%2,%3}, [%4];"
        : "=r"(t0), "=r"(t1), "=r"(t2), "=r"(t3) : "r"(addr));
}
__device__ __forceinline__ void ldsm_x4_trans(uint32_t& t0, uint32_t& t1,
                                              uint32_t& t2, uint32_t& t3,
                                              unsigned addr) {
    asm volatile(
        "ldmatrix.sync.aligned.m8n8.x4.trans.shared.b16 {%0,%1,%2,%3}, [%4];"
        : "=r"(t0), "=r"(t1), "=r"(t2), "=r"(t3) : "r"(addr));
}

// ---------------- tiny prelim kernels --------------------------------------
__global__ void k_query(const float* __restrict__ Lq, const float* __restrict__ Wq,
                        const float* __restrict__ bq, float* __restrict__ Q) {
    const int lane = threadIdx.x & 31;
    const int wg = (blockIdx.x * blockDim.x + threadIdx.x) >> 5;  // 0..511
    for (int o = wg; o < SLOTS * HID; o += 512) {
        const int s = o >> 10, e = o & 1023;
        const float4* a = (const float4*)(Lq + (size_t)s * HID);
        const float4* w = (const float4*)(Wq + (size_t)e * HID);
        float p = 0.f;
        #pragma unroll
        for (int i = 0; i < 8; i++) {
            float4 xa = a[i * 32 + lane];
            float4 xw = w[i * 32 + lane];
            p += xa.x * xw.x + xa.y * xw.y + xa.z * xw.z + xa.w * xw.w;
        }
        #pragma unroll
        for (int off = 16; off; off >>= 1) p += __shfl_xor_sync(0xffffffffu, p, off);
        if (lane == 0) Q[o] = p + bq[e];
    }
}

__global__ void k_qtilde(const float* __restrict__ Q, const float* __restrict__ Wk,
                         const float* __restrict__ bk, float* __restrict__ QT,
                         float* __restrict__ CV) {
    const int s = blockIdx.x >> 2;
    const int chunk = blockIdx.x & 3;
    const int n = chunk * 256 + threadIdx.x;
    __shared__ float qs[HID];
    #pragma unroll
    for (int u = 0; u < 4; u++) qs[u * 256 + threadIdx.x] = Q[s * HID + u * 256 + threadIdx.x];
    __syncthreads();
    float acc = 0.f;
    #pragma unroll 8
    for (int d = 0; d < HID; d++) acc += qs[d] * Wk[(size_t)d * HID + n];
    QT[s * HID + n] = acc;
    if (chunk == 0 && threadIdx.x < 32) {
        float p = 0.f;
        for (int d = threadIdx.x; d < HID; d += 32) p += qs[d] * bk[d];
        #pragma unroll
        for (int off = 16; off; off >>= 1) p += __shfl_xor_sync(0xffffffffu, p, off);
        if (threadIdx.x == 0) CV[s] = p;
    }
}

__global__ void k_cb(const float* __restrict__ Wo, const float* __restrict__ bv,
                     const float* __restrict__ bo, float* __restrict__ CB) {
    const int e = (blockIdx.x * blockDim.x + threadIdx.x) >> 5;
    const int lane = threadIdx.x & 31;
    const float* row = Wo + (size_t)e * HID;
    float p = 0.f;
    for (int d = lane; d < HID; d += 32) p += row[d] * bv[d];
    #pragma unroll
    for (int off = 16; off; off >>= 1) p += __shfl_xor_sync(0xffffffffu, p, off);
    if (lane == 0) CB[e] = p + bo[e];
}

// WvTH[n,d] = fp16(Wv[d,n])
__global__ void k_transposeH(const float* __restrict__ A, __half* __restrict__ AT) {
    __shared__ float t[32][33];
    const int bx = blockIdx.x * 32, by = blockIdx.y * 32;
    const int x = threadIdx.x, y0 = threadIdx.y;
    #pragma unroll
    for (int i = 0; i < 32; i += 8)
        t[y0 + i][x] = A[(size_t)(by + y0 + i) * HID + bx + x];
    __syncthreads();
    #pragma unroll
    for (int i = 0; i < 32; i += 8)
        AT[(size_t)(bx + y0 + i) * HID + by + x] = __float2half_rn(t[x][y0 + i]);
}

// out[i] = fp16(in[i])
__global__ void k_tohalf(const float* __restrict__ in, __half* __restrict__ out) {
    const int i = blockIdx.x * blockDim.x + threadIdx.x;
    float4 f = ((const float4*)in)[i];
    uint2 o;
    o.x = h2bits(__floats2half2_rn(f.x, f.y));
    o.y = h2bits(__floats2half2_rn(f.z, f.w));
    ((uint2*)out)[i] = o;
}

// ---------------- fp16 mma.sync GEMM: D[M,N] = A[M,K] @ B[N,K]^T (+bias) ----
// m16n8k16, fp32 accum. BK=64 halves, double-buffered smem, ldmatrix frags.
template <bool HALF_OUT>
__global__ void __launch_bounds__(256, 2)
hgemm_kernel(const __half* __restrict__ A, const __half* __restrict__ B,
             void* __restrict__ Cv, const float* __restrict__ bias,
             int M, int N, int K) {
    __shared__ __align__(16) uint32_t As[2][4096];   // 128 rows x 32 words
    __shared__ __align__(16) uint32_t Bs[2][4096];

    const int tid = threadIdx.x;
    const int warp = tid >> 5, lane = tid & 31;
    const int m0 = blockIdx.y * 128;
    const int n0 = blockIdx.x * 128;
    const int wm = (warp & 3) * 32;
    const int wn = (warp >> 2) * 64;
    const int qr = lane >> 2;
    const int qc = lane & 3;
    const int lr = (lane & 7) + ((lane >> 3) & 1) * 8;
    const int wgl = (lane >> 4) & 1;

    float acc[2][8][4];
    #pragma unroll
    for (int i = 0; i < 2; i++)
        #pragma unroll
        for (int j = 0; j < 8; j++)
            #pragma unroll
            for (int v = 0; v < 4; v++) acc[i][j][v] = 0.f;

    uint4 pa[4], pb[4];
    #pragma unroll
    for (int u = 0; u < 4; u++) {
        int v = u * 256 + tid;
        int r = v >> 3, g = v & 7;
        pa[u] = *(const uint4*)(A + (size_t)(m0 + r) * K + g * 8);
        pb[u] = *(const uint4*)(B + (size_t)(n0 + r) * K + g * 8);
    }
    #pragma unroll
    for (int u = 0; u < 4; u++) {
        int v = u * 256 + tid;
        int r = v >> 3, g = v & 7;
        int phys = r * 32 + (((g ^ r) & 7) << 2);
        *(uint4*)&As[0][phys] = pa[u];
        *(uint4*)&Bs[0][phys] = pb[u];
    }
    __syncthreads();

    const int ar0 = wm + lr;
    const int ar1 = wm + 16 + lr;
    const int br0 = wn + lr, br1 = wn + 16 + lr, br2 = wn + 32 + lr, br3 = wn + 48 + lr;

    const int nchunk = K / 64;
    #pragma unroll 1
    for (int ck = 0; ck < nchunk; ck++) {
        const int cur = ck & 1;
        if (ck + 1 < nchunk) {
            const int k0 = (ck + 1) * 64;
            #pragma unroll
            for (int u = 0; u < 4; u++) {
                int v = u * 256 + tid;
                int r = v >> 3, g = v & 7;
                pa[u] = *(const uint4*)(A + (size_t)(m0 + r) * K + k0 + g * 8);
                pb[u] = *(const uint4*)(B + (size_t)(n0 + r) * K + k0 + g * 8);
            }
        }
        const unsigned aBase = su32(As[cur]);
        const unsigned bBase = su32(Bs[cur]);
        #pragma unroll
        for (int kk = 0; kk < 4; kk++) {
            const int g = 2 * kk + wgl;
            uint32_t af0[4], af1[4], tb[4];
            ldsm_x4(af0[0], af0[1], af0[2], af0[3],
                    aBase + (unsigned)(ar0 * 128 + (((g ^ ar0) & 7) << 4)));
            ldsm_x4(af1[0], af1[1], af1[2], af1[3],
                    aBase + (unsigned)(ar1 * 128 + (((g ^ ar1) & 7) << 4)));
            const int brs[4] = {br0, br1, br2, br3};
            #pragma unroll
            for (int njb = 0; njb < 4; njb++) {
                const int br = brs[njb];
                ldsm_x4(tb[0], tb[1], tb[2], tb[3],
                        bBase + (unsigned)(br * 128 + (((g ^ br) & 7) << 4)));
                mma_f16(acc[0][2 * njb],     af0, tb[0], tb[2]);
                mma_f16(acc[0][2 * njb + 1], af0, tb[1], tb[3]);
                mma_f16(acc[1][2 * njb],     af1, tb[0], tb[2]);
                mma_f16(acc[1][2 * njb + 1], af1, tb[1], tb[3]);
            }
        }
        if (ck + 1 < nchunk) {
            uint32_t* An = As[cur ^ 1];
            uint32_t* Bn = Bs[cur ^ 1];
            #pragma unroll
            for (int u = 0; u < 4; u++) {
                int v = u * 256 + tid;
                int r = v >> 3, g = v & 7;
                int phys = r * 32 + (((g ^ r) & 7) << 2);
                *(uint4*)&An[phys] = pa[u];
                *(uint4*)&Bn[phys] = pb[u];
            }
        }
        __syncthreads();
    }

    #pragma unroll
    for (int mi = 0; mi < 2; mi++) {
        const int r = m0 + wm + mi * 16 + qr;
        #pragma unroll
        for (int nj = 0; nj < 8; nj++) {
            const int cc = n0 + wn + nj * 8 + 2 * qc;
            float b0 = 0.f, b1 = 0.f;
            if (bias) { b0 = bias[cc]; b1 = bias[cc + 1]; }
            float v00 = acc[mi][nj][0] + b0, v01 = acc[mi][nj][1] + b1;
            float v10 = acc[mi][nj][2] + b0, v11 = acc[mi][nj][3] + b1;
            if (HALF_OUT) {
                __half* C = (__half*)Cv;
                *(__half2*)(C + (size_t)r * N + cc) = __floats2half2_rn(v00, v01);
                *(__half2*)(C + (size_t)(r + 8) * N + cc) = __floats2half2_rn(v10, v11);
            } else {
                float* C = (float*)Cv;
                *(float2*)(C + (size_t)r * N + cc) = make_float2(v00, v01);
                *(float2*)(C + (size_t)(r + 8) * N + cc) = make_float2(v10, v11);
            }
        }
    }
}

// ---------------- attention v6: 512 threads, 16-token subtiles, overlap -----
// Per CTA = one batch; 16 subtiles of 16 tokens, double-buffered fp16 X.
// Next subtile's LDGs issue before current subtile's compute -> loads drain
// under MMA/softmax (in-flight bytes ~64KB/SM vs ~25KB needed for peak DRAM).
//   S[16,16] = QT @ Xsub^T  (16 warps x 64-dim K slices, fp16 partials)
//   w = exp((S + cv)*scale + lg); m[16, band64] += w @ Xsub per warp
#define XSTB 2064                 // X/QT row stride bytes
#define WSB  80                   // ws row stride bytes
#define RSTH 24                   // red row stride halves
// byte offsets
#define A6_QT  0
#define A6_XS  33024              // + 16*2064
#define A6_RED 99072              // + 2*16*2064
#define A6_WS  111360             // + 16*16*24*2
#define A6_LS  112640             // + 16*80
#define A6_CV  112704
#define A6_LG  112768
#define A6_TOTAL 113792           // + 256*4

__global__ void __launch_bounds__(512, 1)
attn6_kernel(const float* __restrict__ X, const float* __restrict__ LG,
             const float* __restrict__ QT, const float* __restrict__ CV,
             __half* __restrict__ Mout) {
    extern __shared__ __align__(16) char smc[];
    float* Ls  = (float*)(smc + A6_LS);
    float* cvs = (float*)(smc + A6_CV);
    float* lgs = (float*)(smc + A6_LG);

    const int b = blockIdx.x;
    const int tid = threadIdx.x;
    const int warp = tid >> 5, lane = tid & 31;
    const int qr = lane >> 2, qc = lane & 3;
    const int band = warp * 64;    // m-GEMM: warp's 64-dim band
    const int lr = (lane & 7) + ((lane >> 3) & 1) * 8;
    const int wgl = (lane >> 4) & 1;

    // stage QT as fp16: v = float4 index over 16x1024; row = v>>8, g = v&255
    const float4* QT4 = (const float4*)QT;
    #pragma unroll
    for (int u = 0; u < 8; u++) {
        int v = u * 512 + tid;
        int s = v >> 8, g = v & 255;
        float4 f = QT4[v];
        uint2 o;
        o.x = h2bits(__floats2half2_rn(f.x, f.y));
        o.y = h2bits(__floats2half2_rn(f.z, f.w));
        *(uint2*)(smc + A6_QT + s * XSTB + g * 8) = o;
    }
    if (tid < 16) { cvs[tid] = CV[tid]; Ls[tid] = 0.f; }
    if (tid < 256) lgs[tid] = LG[b * SEG + tid];

    float macc[8][4];
    #pragma unroll
    for (int i = 0; i < 8; i++)
        #pragma unroll
        for (int v = 0; v < 4; v++) macc[i][v] = 0.f;

    // ldmatrix (trans) lane parts for m-GEMM B frags
    const int row_sel = lane & 7, mat = lane >> 3;
    const int tok_part = ((mat & 1) << 3) + row_sel;
    const int dim_part = (mat >> 1) << 3;

    // score-GEMM ldmatrix row bases
    const unsigned qtB = su32(smc) + A6_QT + (unsigned)(lr * XSTB);

    const float4* Xb4 = (const float4*)(X + (size_t)b * SEG * HID);

    // stage subtile 0 into Xs[0]: v = u*512+tid; tok = v>>8 (0..15), g = v&255
    {
        uint2 ph[8];
        #pragma unroll
        for (int u = 0; u < 8; u++) {
            int v = u * 512 + tid;
            float4 f = Xb4[(v >> 8) * 256 + (v & 255)];
            ph[u].x = h2bits(__floats2half2_rn(f.x, f.y));
            ph[u].y = h2bits(__floats2half2_rn(f.z, f.w));
        }
        #pragma unroll
        for (int u = 0; u < 8; u++) {
            int v = u * 512 + tid;
            *(uint2*)(smc + A6_XS + (v >> 8) * XSTB + (v & 255) * 8) = ph[u];
        }
    }
    __syncthreads();

    #pragma unroll 1
    for (int st = 0; st < 16; st++) {
        const int cur = st & 1;
        const unsigned xsB = su32(smc) + A6_XS + (unsigned)(cur * 16 * XSTB);

        // issue next subtile's loads NOW; they drain under the compute below
        uint2 ph[8];
        if (st + 1 < 16) {
            #pragma unroll
            for (int u = 0; u < 8; u++) {
                int v = u * 512 + tid;
                float4 f = Xb4[((st + 1) * 16 + (v >> 8)) * 256 + (v & 255)];
                ph[u].x = h2bits(__floats2half2_rn(f.x, f.y));
                ph[u].y = h2bits(__floats2half2_rn(f.z, f.w));
            }
        }

        // ---- score GEMM: warp K-slice [warp*64, +64) ----
        float sacc[2][4];
        #pragma unroll
        for (int j = 0; j < 2; j++)
            #pragma unroll
            for (int v = 0; v < 4; v++) sacc[j][v] = 0.f;
        #pragma unroll
        for (int kk = 0; kk < 4; kk++) {
            const unsigned kb2 = (unsigned)((warp * 64 + kk * 16 + wgl * 8) * 2);
            uint32_t a[4], t[4];
            ldsm_x4(a[0], a[1], a[2], a[3], qtB + kb2);
            ldsm_x4(t[0], t[1], t[2], t[3], xsB + (unsigned)(lr * XSTB) + kb2);
            mma_f16(sacc[0], a, t[0], t[2]);
            mma_f16(sacc[1], a, t[1], t[3]);
        }
        // write fp16 partials: red[warp][slot row][tok]
        #pragma unroll
        for (int nj = 0; nj < 2; nj++) {
            const int col = nj * 8 + 2 * qc;
            *(__half2*)(smc + A6_RED + (warp * 384 + qr * RSTH + col) * 2) =
                __floats2half2_rn(sacc[nj][0], sacc[nj][1]);
            *(__half2*)(smc + A6_RED + (warp * 384 + (qr + 8) * RSTH + col) * 2) =
                __floats2half2_rn(sacc[nj][2], sacc[nj][3]);
        }
        __syncthreads();

        // ---- reduce + softmax weights (tid<256: one (slot,tok) each) ----
        if (tid < 256) {
            const int row = tid >> 4, tok = tid & 15;
            float s = 0.f;
            #pragma unroll
            for (int w = 0; w < 16; w++)
                s += __half2float(*(const __half*)(
                    smc + A6_RED + (w * 384 + row * RSTH + tok) * 2));
            float sc = (s + cvs[row]) * 0.03125f + lgs[st * 16 + tok];
            *(__half*)(smc + A6_WS + row * WSB + tok * 2) =
                __float2half_rn(__expf(sc));
        }
        __syncthreads();

        // Ls accumulation: warp w handles slot w (lanes 0..15)
        if (lane < 16) {
            float wv = __half2float(*(const __half*)(
                smc + A6_WS + warp * WSB + lane * 2));
            #pragma unroll
            for (int off = 8; off; off >>= 1)
                wv += __shfl_xor_sync(0x0000ffffu, wv, off);
            if (lane == 0) Ls[warp] += wv;
        }

        // ---- m GEMM: m[16, band..band+64) += w[16,16] @ Xsub ----
        {
            uint32_t a[4];
            a[0] = *(const uint32_t*)(smc + A6_WS + qr * WSB + (2 * qc) * 2);
            a[1] = *(const uint32_t*)(smc + A6_WS + (qr + 8) * WSB + (2 * qc) * 2);
            a[2] = *(const uint32_t*)(smc + A6_WS + qr * WSB + (2 * qc) * 2 + 16);
            a[3] = *(const uint32_t*)(smc + A6_WS + (qr + 8) * WSB + (2 * qc) * 2 + 16);
            #pragma unroll
            for (int njb = 0; njb < 4; njb++) {
                unsigned addr = xsB + (unsigned)(tok_part * XSTB +
                                     (band + njb * 16 + dim_part) * 2);
                uint32_t t0, t1, t2, t3;
                ldsm_x4_trans(t0, t1, t2, t3, addr);
                mma_f16(macc[2 * njb],     a, t0, t1);
                mma_f16(macc[2 * njb + 1], a, t2, t3);
            }
        }

        // ---- store prefetched subtile into the other buffer ----
        if (st + 1 < 16) {
            #pragma unroll
            for (int u = 0; u < 8; u++) {
                int v = u * 512 + tid;
                *(uint2*)(smc + A6_XS + ((cur ^ 1) * 16 + (v >> 8)) * XSTB +
                          (v & 255) * 8) = ph[u];
            }
        }
        __syncthreads();
    }

    const float inv0 = 1.0f / Ls[qr];
    const float inv1 = 1.0f / Ls[qr + 8];
    __half* m0p = Mout + ((size_t)b * SLOTS + qr) * HID;
    __half* m1p = Mout + ((size_t)b * SLOTS + qr + 8) * HID;
    #pragma unroll
    for (int nj = 0; nj < 8; nj++) {
        const int cc = band + nj * 8 + 2 * qc;
        *(__half2*)(m0p + cc) =
            __floats2half2_rn(macc[nj][0] * inv0, macc[nj][1] * inv0);
        *(__half2*)(m1p + cc) =
            __floats2half2_rn(macc[nj][2] * inv1, macc[nj][3] * inv1);
    }
}

// ---------------- launcher ---------------------------------------------------
extern "C" void kernel_launch(void* const* d_in, const int* in_sizes, int n_in,
                              void* d_out, int out_size) {
    (void)in_sizes; (void)n_in; (void)out_size;
    const float* X  = (const float*)d_in[0];   // segment_states [512,256,1024]
    const float* LG = (const float*)d_in[1];   // importance_logits [512,256]
    const float* Lq = (const float*)d_in[2];   // latent_queries [16,1024]
    const float* Wq = (const float*)d_in[3];
    const float* bq = (const float*)d_in[4];
    const float* Wk = (const float*)d_in[5];
    const float* bk = (const float*)d_in[6];
    const float* Wv = (const float*)d_in[7];
    const float* bv = (const float*)d_in[8];
    const float* Wo = (const float*)d_in[9];
    const float* bo = (const float*)d_in[10];
    float* out = (float*)d_out;

    void *pQ, *pQT, *pC, *pCB, *pWcH, *pWvTH, *pWoH, *pMH;
    cudaGetSymbolAddress(&pQ, g_query);
    cudaGetSymbolAddress(&pQT, g_qt);
    cudaGetSymbolAddress(&pC, g_c);
    cudaGetSymbolAddress(&pCB, g_cb);
    cudaGetSymbolAddress(&pWcH, g_WcH);
    cudaGetSymbolAddress(&pWvTH, g_WvTH);
    cudaGetSymbolAddress(&pWoH, g_WoH);
    cudaGetSymbolAddress(&pMH, g_mH);
    float*  Q    = (float*)pQ;
    float*  QT   = (float*)pQT;
    float*  C    = (float*)pC;
    float*  CB   = (float*)pCB;
    __half* WcH  = (__half*)pWcH;
    __half* WvTH = (__half*)pWvTH;
    __half* WoH  = (__half*)pWoH;
    __half* MH   = (__half*)pMH;

    cudaFuncSetAttribute(attn6_kernel, cudaFuncAttributeMaxDynamicSharedMemorySize,
                         A6_TOTAL);

    // order: hgemm_Wc sits in the ncu-profiled slot (#4)
    k_transposeH<<<dim3(32, 32), dim3(32, 8)>>>(Wv, WvTH);
    k_tohalf<<<(HID * HID / 4) / 256, 256>>>(Wo, WoH);
    k_query<<<64, 256>>>(Lq, Wq, bq, Q);
    // Wc = Wo @ Wv  (fp16 GEMM, fp16 output) -- PROFILED
    hgemm_kernel<true><<<dim3(HID / 128, HID / 128), 256>>>(
        WoH, WvTH, WcH, nullptr, HID, HID, HID);
    k_qtilde<<<64, 256>>>(Q, Wk, bk, QT, C);
    k_cb<<<128, 256>>>(Wo, bv, bo, CB);
    // attention -> m  (fp16 tensor cores, overlapped streaming)
    attn6_kernel<<<BSZ, 512, A6_TOTAL>>>(X, LG, QT, C, MH);
    // out = m @ Wc^T + cb  (fp16 GEMM, fp32 output)
    hgemm_kernel<false><<<dim3(HID / 128, (BSZ * SLOTS) / 128), 256>>>(
        MH, WcH, out, CB, BSZ * SLOTS, HID, HID);
}